// round 15
// baseline (speedup 1.0000x reference)
#include <cuda_runtime.h>
#include <cuda_fp16.h>
#include <cstdint>

#define DD 128
#define MAX_R 8
#define MAX_N 50000
#define NG 9                    // 8 relations + self (W0)
#define RN (MAX_R * MAX_N)      // 400000 segments
#define MAX_E 1000000

// ---------------- device scratch (no allocs allowed) ----------------
__device__ __half g_x16[(size_t)MAX_N * DD];            // fp16 X, 12.8 MB (L2-resident)
__device__ __half g_wh [(size_t)NG * DD * DD];          // fp16 W^T, [g][n][k]
__device__ int    g_cnt[RN];                            // counts -> cursors -> ends
__device__ int    g_start[RN];                          // segment range starts
__device__ int    g_cursor;                             // global range allocator
__device__ int    g_srcs[MAX_E];                        // segment-sorted src indices

__device__ __forceinline__ uint32_t smem_u32(const void* p) {
    uint32_t a;
    asm("{ .reg .u64 t; cvta.to.shared.u64 t, %1; cvt.u32.u64 %0, t; }" : "=r"(a) : "l"(p));
    return a;
}

// ---------------- prep: zero seg counters + fp16(X) + fp16(W^T) ----------------
#define CZ (RN / 4)                                     // 100,000 uint4 counter zeros
#define XC (MAX_N * DD / 8)                             // 800,000 x-convert items
#define WC (NG * DD * DD)                               // 147,456 w-convert scalars
__global__ void prep_kernel(const float* __restrict__ X,
                            const float* __restrict__ W,
                            const float* __restrict__ W0)
{
    int i = blockIdx.x * blockDim.x + threadIdx.x;
    if (i < CZ) {
        ((uint4*)g_cnt)[i] = make_uint4(0, 0, 0, 0);
    } else if (i < CZ + XC) {
        int j = i - CZ;                                  // 8 floats -> 8 halves
        float4 f0 = ((const float4*)X)[j * 2];
        float4 f1 = ((const float4*)X)[j * 2 + 1];
        uint4 o;
        *(__half2*)&o.x = __floats2half2_rn(f0.x, f0.y);
        *(__half2*)&o.y = __floats2half2_rn(f0.z, f0.w);
        *(__half2*)&o.z = __floats2half2_rn(f1.x, f1.y);
        *(__half2*)&o.w = __floats2half2_rn(f1.z, f1.w);
        ((uint4*)g_x16)[j] = o;
    } else if (i < CZ + XC + WC) {
        int j = i - CZ - XC;
        int g = j / (DD * DD);
        int rem = j - g * DD * DD;
        int n = rem >> 7, k = rem & 127;                 // dest layout [g][n][k]
        float w = (g < MAX_R) ? W[(size_t)g * DD * DD + (size_t)k * DD + n]
                              : W0[(size_t)k * DD + n];
        g_wh[j] = __float2half_rn(w);
    } else if (i == CZ + XC + WC) {
        g_cursor = 0;
    }
}

// ---------------- CSR pass A: per-segment edge counts ----------------
__global__ void count_kernel(const int* __restrict__ edst,
                             const int* __restrict__ erel, int E, int N)
{
    int e = blockIdx.x * blockDim.x + threadIdx.x;
    if (e >= E) return;
    atomicAdd(&g_cnt[erel[e] * N + edst[e]], 1);
}

// ---------------- CSR pass B: disjoint range allocation ----------------
__global__ __launch_bounds__(1024)
void offsets_kernel()
{
    __shared__ int wsum[32], wbase[32], bbase;
    int t = threadIdx.x, lane = t & 31, wid = t >> 5;
    int i = blockIdx.x * 1024 + t;
    int c = (i < RN) ? g_cnt[i] : 0;
    int incl = c;
    #pragma unroll
    for (int o = 1; o < 32; o <<= 1) {
        int nv = __shfl_up_sync(0xffffffffu, incl, o);
        if (lane >= o) incl += nv;
    }
    if (lane == 31) wsum[wid] = incl;
    __syncthreads();
    if (wid == 0) {
        int v = wsum[lane];
        int wi = v;
        #pragma unroll
        for (int o = 1; o < 32; o <<= 1) {
            int nv = __shfl_up_sync(0xffffffffu, wi, o);
            if (lane >= o) wi += nv;
        }
        wbase[lane] = wi - v;
        if (lane == 31) bbase = atomicAdd(&g_cursor, wi);
    }
    __syncthreads();
    if (i < RN) {
        int st = bbase + wbase[wid] + (incl - c);
        g_start[i] = st;
        g_cnt[i] = st;                                   // reuse as running cursor
    }
}

// ---------------- CSR pass C: reorder src indices ----------------
__global__ void reorder_kernel(const int* __restrict__ esrc,
                               const int* __restrict__ edst,
                               const int* __restrict__ erel, int E, int N)
{
    int e = blockIdx.x * blockDim.x + threadIdx.x;
    if (e >= E) return;
    int seg = erel[e] * N + edst[e];
    int pos = atomicAdd(&g_cnt[seg], 1);                 // after: g_cnt[seg] == end
    g_srcs[pos] = esrc[e];
}

// ---------------- warp-specialized fused gather-GEMM ----------------
// out = X@W0 + sum_r diag(inv_norm_r)(A_r@X) @ W_r.
// warps 0-7: consumers (MMA, 32x64 tiles). warps 8-15: producers (segment
// gather from L2-resident g_x16 into a 2-buffer A ring). Handshake via
// named barriers; producer memory stalls never block consumer MMA issue.
#define SM_A0 0
#define SM_B0 65536
#define SMEM_TOTAL 163840
// named barrier ids (0 reserved)
#define BAR_FULL0 1
#define BAR_FULL1 2
#define BAR_EMPTY0 3
#define BAR_EMPTY1 4
#define BAR_BCONS 5

#define NBAR_SYNC(id, cnt)   asm volatile("bar.sync %0, %1;"   :: "r"(id), "r"(cnt) : "memory")
#define NBAR_ARRIVE(id, cnt) asm volatile("bar.arrive %0, %1;" :: "r"(id), "r"(cnt) : "memory")

__device__ __forceinline__ void cp16(uint32_t dst, const void* src) {
    asm volatile("cp.async.cg.shared.global [%0], [%1], 16;"
                 :: "r"(dst), "l"(src) : "memory");
}
#define CP_COMMIT() asm volatile("cp.async.commit_group;" ::: "memory")
#define CP_WAIT(n)  asm volatile("cp.async.wait_group %0;" :: "n"(n) : "memory")

__device__ __forceinline__ void ldmx4(uint32_t* r, uint32_t addr) {
    asm volatile("ldmatrix.sync.aligned.m8n8.x4.shared.b16 {%0,%1,%2,%3}, [%4];"
                 : "=r"(r[0]), "=r"(r[1]), "=r"(r[2]), "=r"(r[3]) : "r"(addr));
}
__device__ __forceinline__ void mma16816h(float* c, const uint32_t* a,
                                          uint32_t b0, uint32_t b1) {
    asm volatile("mma.sync.aligned.m16n8k16.row.col.f32.f16.f16.f32 "
                 "{%0,%1,%2,%3}, {%4,%5,%6,%7}, {%8,%9}, {%0,%1,%2,%3};"
                 : "+f"(c[0]), "+f"(c[1]), "+f"(c[2]), "+f"(c[3])
                 : "r"(a[0]), "r"(a[1]), "r"(a[2]), "r"(a[3]), "r"(b0), "r"(b1));
}

__global__ __launch_bounds__(512, 1)
void fused_kernel(const float* __restrict__ inv_norm, float* __restrict__ out, int N)
{
    extern __shared__ char smem[];
    uint32_t sb = smem_u32(smem);
    const int t = threadIdx.x, ln = t & 31, wid = t >> 5;
    const int row0 = blockIdx.x * 128;

    if (wid >= 8) {
        // ================= PRODUCER (warps 8-15) =================
        const int pt = t - 256;              // 0..255
        const int half_id = pt >> 4;         // 0..15 half-warps
        const int half = pt & 15;            // 16B chunk in 256B row

        // builds one A tile (128 rows) for group g into ring buffer buf
        auto buildA = [&](int g, int buf) {
            char* aBuf = smem + SM_A0 + buf * 32768;
            #pragma unroll
            for (int it = 0; it < 8; ++it) {
                int row = half_id + it * 16;
                int gr = row0 + row;
                uint32_t dst = (uint32_t)(row * 256 + ((half * 16) ^ ((row & 7) << 4)));
                uint4 o = make_uint4(0, 0, 0, 0);
                if (gr < N) {
                    if (g == MAX_R) {
                        o = __ldg((const uint4*)(g_x16 + (size_t)gr * DD) + half);
                    } else {
                        int seg = g * N + gr;
                        int s0 = __ldg(&g_start[seg]);
                        int s1 = __ldg(&g_cnt[seg]);
                        if (s1 > s0) {
                            float a0=0.f,a1=0.f,a2=0.f,a3=0.f,a4=0.f,a5=0.f,a6=0.f,a7=0.f;
                            float b0=0.f,b1=0.f,b2=0.f,b3=0.f,b4=0.f,b5=0.f,b6=0.f,b7=0.f;
                            int e = s0;
                            for (; e + 1 < s1; e += 2) {   // 2 independent chains
                                int sA = __ldg(&g_srcs[e]);
                                int sB = __ldg(&g_srcs[e + 1]);
                                uint4 vA = __ldg((const uint4*)(g_x16 + (size_t)sA * DD) + half);
                                uint4 vB = __ldg((const uint4*)(g_x16 + (size_t)sB * DD) + half);
                                float2 f;
                                f = __half22float2(*(__half2*)&vA.x); a0 += f.x; a1 += f.y;
                                f = __half22float2(*(__half2*)&vA.y); a2 += f.x; a3 += f.y;
                                f = __half22float2(*(__half2*)&vA.z); a4 += f.x; a5 += f.y;
                                f = __half22float2(*(__half2*)&vA.w); a6 += f.x; a7 += f.y;
                                f = __half22float2(*(__half2*)&vB.x); b0 += f.x; b1 += f.y;
                                f = __half22float2(*(__half2*)&vB.y); b2 += f.x; b3 += f.y;
                                f = __half22float2(*(__half2*)&vB.z); b4 += f.x; b5 += f.y;
                                f = __half22float2(*(__half2*)&vB.w); b6 += f.x; b7 += f.y;
                            }
                            if (e < s1) {
                                int sA = __ldg(&g_srcs[e]);
                                uint4 vA = __ldg((const uint4*)(g_x16 + (size_t)sA * DD) + half);
                                float2 f;
                                f = __half22float2(*(__half2*)&vA.x); a0 += f.x; a1 += f.y;
                                f = __half22float2(*(__half2*)&vA.y); a2 += f.x; a3 += f.y;
                                f = __half22float2(*(__half2*)&vA.z); a4 += f.x; a5 += f.y;
                                f = __half22float2(*(__half2*)&vA.w); a6 += f.x; a7 += f.y;
                            }
                            float sc = __ldg(&inv_norm[seg]);
                            *(__half2*)&o.x = __floats2half2_rn((a0+b0)*sc, (a1+b1)*sc);
                            *(__half2*)&o.y = __floats2half2_rn((a2+b2)*sc, (a3+b3)*sc);
                            *(__half2*)&o.z = __floats2half2_rn((a4+b4)*sc, (a5+b5)*sc);
                            *(__half2*)&o.w = __floats2half2_rn((a6+b6)*sc, (a7+b7)*sc);
                        }
                    }
                }
                *(uint4*)(aBuf + dst) = o;
            }
        };

        buildA(0, 0); NBAR_ARRIVE(BAR_FULL0, 512);
        buildA(1, 1); NBAR_ARRIVE(BAR_FULL1, 512);
        for (int g = 2; g < NG; ++g) {
            int buf = g & 1;
            NBAR_SYNC(buf ? BAR_EMPTY1 : BAR_EMPTY0, 512);   // consumers done with buf
            buildA(g, buf);
            NBAR_ARRIVE(buf ? BAR_FULL1 : BAR_FULL0, 512);
        }
        return;   // producers exit; all their barrier arrivals are complete
    }

    // ================= CONSUMER (warps 0-7) =================
    // B loader geometry: 256 threads x 16B, rows stride 16 (8 iters)
    const int kb = (t & 15) * 16;
    const int colh = kb >> 1;
    const int rbase = t >> 4;            // 0..15
    auto cpB = [&](int g, int buf) {
        const __half* B = g_wh + (size_t)g * DD * DD;
        uint32_t bBuf = sb + SM_B0 + buf * 32768;
        #pragma unroll
        for (int it = 0; it < 8; ++it) {
            int row = rbase + it * 16;
            uint32_t dst = (uint32_t)(row * 256 + (kb ^ ((row & 7) << 4)));
            cp16(bBuf + dst, B + (size_t)row * DD + colh);
        }
    };

    float c[2][8][4];
    #pragma unroll
    for (int mi = 0; mi < 2; ++mi)
        #pragma unroll
        for (int j = 0; j < 8; ++j)
            #pragma unroll
            for (int q = 0; q < 4; ++q) c[mi][j][q] = 0.f;

    const int m0 = (wid & 3) * 32;       // 4 M-warps
    const int n0 = (wid >> 2) * 64;      // 2 N-warps
    const int rA   = ln & 15;
    const int koff = ln & 16;

    cpB(0, 0); CP_COMMIT();
    cpB(1, 1); CP_COMMIT();
    cpB(2, 2); CP_COMMIT();

    for (int g = 0; g < NG; ++g) {
        if (g <= NG - 3)      { CP_WAIT(2); }
        else if (g == NG - 2) { CP_WAIT(1); }
        else                  { CP_WAIT(0); }
        NBAR_SYNC(BAR_BCONS, 256);                       // B(g) visible to all consumers
        int abuf = g & 1;
        NBAR_SYNC(abuf ? BAR_FULL1 : BAR_FULL0, 512);    // A(g) ready (producer arrived)

        uint32_t aBase = sb + SM_A0 + abuf * 32768;
        uint32_t bBase = sb + SM_B0 + (g % 3) * 32768;
        #pragma unroll
        for (int ks = 0; ks < 8; ++ks) {
            int kbb = ks * 32;
            uint32_t ah[8], b[16];
            #pragma unroll
            for (int mi = 0; mi < 2; ++mi) {
                int r = m0 + mi * 16 + rA;
                ldmx4(ah + mi * 4, aBase + r * 256 + ((kbb + koff) ^ ((r & 7) << 4)));
            }
            #pragma unroll
            for (int j2 = 0; j2 < 4; ++j2) {
                int r = n0 + j2 * 16 + rA;
                ldmx4(b + j2 * 4, bBase + r * 256 + ((kbb + koff) ^ ((r & 7) << 4)));
            }
            #pragma unroll
            for (int mi = 0; mi < 2; ++mi)
                #pragma unroll
                for (int j2 = 0; j2 < 4; ++j2) {
                    mma16816h(c[mi][2 * j2],     ah + mi * 4, b[j2 * 4 + 0], b[j2 * 4 + 2]);
                    mma16816h(c[mi][2 * j2 + 1], ah + mi * 4, b[j2 * 4 + 1], b[j2 * 4 + 3]);
                }
        }
        NBAR_ARRIVE(abuf ? BAR_EMPTY1 : BAR_EMPTY0, 512);  // release A buffer
        if (g + 3 < NG) { cpB(g + 3, g % 3); CP_COMMIT(); }
    }

    // epilogue: fp32 result -> out (consumers only)
    #pragma unroll
    for (int mi = 0; mi < 2; ++mi) {
        int r0 = row0 + m0 + mi * 16 + (ln >> 2);
        #pragma unroll
        for (int j = 0; j < 8; ++j) {
            int colo = n0 + j * 8 + (ln & 3) * 2;
            if (r0 < N)
                *(float2*)(out + (size_t)r0 * DD + colo) = make_float2(c[mi][j][0], c[mi][j][1]);
            if (r0 + 8 < N)
                *(float2*)(out + (size_t)(r0 + 8) * DD + colo) = make_float2(c[mi][j][2], c[mi][j][3]);
        }
    }
}

extern "C" void kernel_launch(void* const* d_in, const int* in_sizes, int n_in,
                              void* d_out, int out_size)
{
    const float* X        = (const float*)d_in[0];
    const float* W        = (const float*)d_in[1];
    const float* W0       = (const float*)d_in[2];
    const float* inv_norm = (const float*)d_in[3];
    const int*   esrc     = (const int*)d_in[4];
    const int*   edst     = (const int*)d_in[5];
    const int*   erel     = (const int*)d_in[6];
    float* out = (float*)d_out;

    int N = in_sizes[0] / DD;            // 50000
    int E = in_sizes[4];                 // 800000

    // Phase 0: prep (zero counters + cursor, fp16 X, fp16 W^T)
    int prep_items = CZ + XC + WC + 1;
    prep_kernel<<<(prep_items + 255) / 256, 256>>>(X, W, W0);

    // Phase 1: CSR build
    count_kernel<<<(E + 255) / 256, 256>>>(edst, erel, E, N);
    offsets_kernel<<<(RN + 1023) / 1024, 1024>>>();
    reorder_kernel<<<(E + 255) / 256, 256>>>(esrc, edst, erel, E, N);

    // Phase 2: warp-specialized fused gather-GEMM (no agg intermediate)
    cudaFuncSetAttribute(fused_kernel, cudaFuncAttributeMaxDynamicSharedMemorySize, SMEM_TOTAL);
    fused_kernel<<<(N + 127) / 128, 512, SMEM_TOTAL>>>(inv_norm, out, N);
}

// round 17
// speedup vs baseline: 1.7435x; 1.7435x over previous
#include <cuda_runtime.h>
#include <cuda_fp16.h>
#include <cstdint>

#define DD 128
#define MAX_R 8
#define MAX_N 50000
#define NG 9           // 8 relations + self (W0)

// ---------------- device scratch (no allocs allowed) ----------------
__device__ __half g_agg[(size_t)MAX_R * MAX_N * DD];    // pre-scaled per-(rel,dst) sums, 102.4 MB
__device__ __half g_x16[(size_t)MAX_N * DD];            // fp16 X, 12.8 MB (L2-resident)
__device__ __half g_wh [(size_t)NG * DD * DD];          // fp16 W^T, [g][n][k]

__device__ __forceinline__ uint32_t smem_u32(const void* p) {
    uint32_t a;
    asm("{ .reg .u64 t; cvta.to.shared.u64 t, %1; cvt.u32.u64 %0, t; }" : "=r"(a) : "l"(p));
    return a;
}

// ---------------- fused prep: zero agg + fp16(X) + fp16(W^T) ----------------
// (R8 form: one independent 16B store per thread — measured 23.3us)
#define ZA ((int)((size_t)MAX_R * MAX_N * DD / 8))      // 6,400,000 uint4 zero items
#define XC (MAX_N * DD / 8)                             // 800,000 x-convert items (8 floats each)
#define WC (NG * DD * DD)                               // 147,456 w-convert scalars
__global__ void prep_kernel(const float* __restrict__ X,
                            const float* __restrict__ W,
                            const float* __restrict__ W0)
{
    int i = blockIdx.x * blockDim.x + threadIdx.x;
    if (i < ZA) {
        ((uint4*)g_agg)[i] = make_uint4(0, 0, 0, 0);
    } else if (i < ZA + XC) {
        int j = i - ZA;                                  // 8 floats -> 8 halves (one uint4)
        float4 f0 = ((const float4*)X)[j * 2];
        float4 f1 = ((const float4*)X)[j * 2 + 1];
        uint4 o;
        *(__half2*)&o.x = __floats2half2_rn(f0.x, f0.y);
        *(__half2*)&o.y = __floats2half2_rn(f0.z, f0.w);
        *(__half2*)&o.z = __floats2half2_rn(f1.x, f1.y);
        *(__half2*)&o.w = __floats2half2_rn(f1.z, f1.w);
        ((uint4*)g_x16)[j] = o;
    } else if (i < ZA + XC + WC) {
        int j = i - ZA - XC;
        int g = j / (DD * DD);
        int rem = j - g * DD * DD;
        int n = rem >> 7, k = rem & 127;                 // dest layout [g][n][k]
        float w = (g < MAX_R) ? W[(size_t)g * DD * DD + (size_t)k * DD + n]
                              : W0[(size_t)k * DD + n];
        g_wh[j] = __float2half_rn(w);
    }
}

// ---------------- edge scatter: agg[r,dst] += inv_norm[r,dst] * X16[src] ----------------
// Half-warp per edge, 4 edges batched per half-warp (MLP=4 on L2-resident gathers).
#define EPH 4
__global__ void scatter_kernel(const int* __restrict__ esrc,
                               const int* __restrict__ edst,
                               const int* __restrict__ erel,
                               const float* __restrict__ inv_norm,
                               int E, int N)
{
    int warp = blockIdx.x * (blockDim.x >> 5) + (threadIdx.x >> 5);
    int lane = threadIdx.x & 31;
    int h = lane >> 4;              // half-warp id
    int half = lane & 15;
    int e0 = warp * (2 * EPH);

    uint4 v[EPH];
    __half2 s2[EPH];
    long long off[EPH];
    #pragma unroll
    for (int i = 0; i < EPH; ++i) {
        int e = e0 + i * 2 + h;
        if (e < E) {
            int s = __ldg(&esrc[e]);
            int d = __ldg(&edst[e]);
            int r = __ldg(&erel[e]);
            float sc = __ldg(&inv_norm[(size_t)r * N + d]);
            s2[i] = __float2half2_rn(sc);
            v[i]  = __ldg((const uint4*)(g_x16 + (size_t)s * DD) + half);
            off[i] = ((long long)r * N + d) * DD + half * 8;
        } else off[i] = -1;
    }
    #pragma unroll
    for (int i = 0; i < EPH; ++i) {
        if (off[i] >= 0) {
            uint4 av = v[i];
            *(__half2*)&av.x = __hmul2(*(__half2*)&av.x, s2[i]);
            *(__half2*)&av.y = __hmul2(*(__half2*)&av.y, s2[i]);
            *(__half2*)&av.z = __hmul2(*(__half2*)&av.z, s2[i]);
            *(__half2*)&av.w = __hmul2(*(__half2*)&av.w, s2[i]);
            asm volatile("red.global.add.noftz.v4.f16x2 [%0], {%1, %2, %3, %4};"
                         :: "l"(g_agg + off[i]), "r"(av.x), "r"(av.y), "r"(av.z), "r"(av.w)
                         : "memory");
        }
    }
}

// ---------------- GEMM: out = X@W0 + sum_r agg_r @ W_r  (agg pre-scaled) ----------------
// 256 threads, warp tile 32x64, cp.async 2-stage pipeline (R8 config, measured best).
#define STAGE_BYTES 65536
#define SMEM_TOTAL  131072

__device__ __forceinline__ void cp16(uint32_t dst, const void* src, int bytes) {
    asm volatile("cp.async.cg.shared.global [%0], [%1], 16, %2;"
                 :: "r"(dst), "l"(src), "r"(bytes) : "memory");
}
#define CP_COMMIT() asm volatile("cp.async.commit_group;" ::: "memory")
#define CP_WAIT(n)  asm volatile("cp.async.wait_group %0;" :: "n"(n) : "memory")

__device__ __forceinline__ void ldmx4(uint32_t* r, uint32_t addr) {
    asm volatile("ldmatrix.sync.aligned.m8n8.x4.shared.b16 {%0,%1,%2,%3}, [%4];"
                 : "=r"(r[0]), "=r"(r[1]), "=r"(r[2]), "=r"(r[3]) : "r"(addr));
}
__device__ __forceinline__ void mma16816h(float* c, const uint32_t* a,
                                          uint32_t b0, uint32_t b1) {
    asm volatile("mma.sync.aligned.m16n8k16.row.col.f32.f16.f16.f32 "
                 "{%0,%1,%2,%3}, {%4,%5,%6,%7}, {%8,%9}, {%0,%1,%2,%3};"
                 : "+f"(c[0]), "+f"(c[1]), "+f"(c[2]), "+f"(c[3])
                 : "r"(a[0]), "r"(a[1]), "r"(a[2]), "r"(a[3]), "r"(b0), "r"(b1));
}
__device__ __forceinline__ void stg_cs2(float* p, float x, float y) {
    asm volatile("st.global.cs.v2.f32 [%0], {%1, %2};" :: "l"(p), "f"(x), "f"(y) : "memory");
}

__global__ __launch_bounds__(256, 1)
void gemm_fused_kernel(float* __restrict__ out, int N)
{
    extern __shared__ char smem[];
    uint32_t sb = smem_u32(smem);
    const int t = threadIdx.x, ln = t & 31, wid = t >> 5;
    const int row0 = blockIdx.x * 128;

    // loader geometry: 16B chunk per thread, rows stride 16 (8 iters)
    const int kb  = (t & 15) * 16;           // byte offset in 256B row
    const int col = kb >> 1;                 // half index
    const int rbase = t >> 4;                // row 0..15

    auto issue = [&](int g, int buf) {
        const __half* A = (g < MAX_R) ? (g_agg + (size_t)g * (size_t)N * DD) : g_x16;
        const __half* B = g_wh + (size_t)g * DD * DD;
        uint32_t aBuf = sb + buf * STAGE_BYTES;
        uint32_t bBuf = aBuf + 32768;
        #pragma unroll
        for (int it = 0; it < 8; ++it) {
            int row = rbase + it * 16;
            int gr = row0 + row;
            uint32_t dst = (uint32_t)(row * 256 + (kb ^ ((row & 7) << 4)));
            int ok = (gr < N);
            const __half* ap = A + (size_t)(ok ? gr : 0) * DD + col;
            cp16(aBuf + dst, ap, ok ? 16 : 0);           // zero-fill tail rows
            cp16(bBuf + dst, B + (size_t)row * DD + col, 16);
        }
    };

    float c[2][8][4];
    #pragma unroll
    for (int mi = 0; mi < 2; ++mi)
        #pragma unroll
        for (int j = 0; j < 8; ++j)
            #pragma unroll
            for (int q = 0; q < 4; ++q) c[mi][j][q] = 0.f;

    const int m0 = (wid & 3) * 32;     // 4 M-warps
    const int n0 = (wid >> 2) * 64;    // 2 N-warps
    const int rA   = ln & 15;
    const int koff = ln & 16;

    issue(0, 0); CP_COMMIT();
    issue(1, 1); CP_COMMIT();

    for (int g = 0; g < NG; ++g) {
        if (g < NG - 1) { CP_WAIT(1); } else { CP_WAIT(0); }   // stage g resident
        __syncthreads();

        uint32_t aBase = sb + (g & 1) * STAGE_BYTES;
        uint32_t bBase = aBase + 32768;
        #pragma unroll
        for (int ks = 0; ks < 8; ++ks) {
            int kbb = ks * 32;
            uint32_t ah[8], b[16];
            #pragma unroll
            for (int mi = 0; mi < 2; ++mi) {
                int r = m0 + mi * 16 + rA;
                ldmx4(ah + mi * 4, aBase + r * 256 + ((kbb + koff) ^ ((r & 7) << 4)));
            }
            #pragma unroll
            for (int j2 = 0; j2 < 4; ++j2) {
                int r = n0 + j2 * 16 + rA;
                ldmx4(b + j2 * 4, bBase + r * 256 + ((kbb + koff) ^ ((r & 7) << 4)));
            }
            #pragma unroll
            for (int mi = 0; mi < 2; ++mi)
                #pragma unroll
                for (int j2 = 0; j2 < 4; ++j2) {
                    mma16816h(c[mi][2 * j2],     ah + mi * 4, b[j2 * 4 + 0], b[j2 * 4 + 2]);
                    mma16816h(c[mi][2 * j2 + 1], ah + mi * 4, b[j2 * 4 + 1], b[j2 * 4 + 3]);
                }
        }
        __syncthreads();                                   // readers done with stage g
        if (g + 2 < NG) { issue(g + 2, g & 1); CP_COMMIT(); }
    }

    // epilogue: fp32 result -> out (evict-first: out is never re-read)
    #pragma unroll
    for (int mi = 0; mi < 2; ++mi) {
        int r0 = row0 + m0 + mi * 16 + (ln >> 2);
        #pragma unroll
        for (int j = 0; j < 8; ++j) {
            int colo = n0 + j * 8 + (ln & 3) * 2;
            if (r0 < N)
                stg_cs2(out + (size_t)r0 * DD + colo, c[mi][j][0], c[mi][j][1]);
            if (r0 + 8 < N)
                stg_cs2(out + (size_t)(r0 + 8) * DD + colo, c[mi][j][2], c[mi][j][3]);
        }
    }
}

extern "C" void kernel_launch(void* const* d_in, const int* in_sizes, int n_in,
                              void* d_out, int out_size)
{
    const float* X        = (const float*)d_in[0];
    const float* W        = (const float*)d_in[1];
    const float* W0       = (const float*)d_in[2];
    const float* inv_norm = (const float*)d_in[3];
    const int*   esrc     = (const int*)d_in[4];
    const int*   edst     = (const int*)d_in[5];
    const int*   erel     = (const int*)d_in[6];
    float* out = (float*)d_out;

    int N = in_sizes[0] / DD;            // 50000
    int E = in_sizes[4];                 // 800000

    // Phase 0: fused prep (zero agg + fp16 X + fp16 W^T)
    int prep_items = ZA + XC + WC;
    prep_kernel<<<(prep_items + 255) / 256, 256>>>(X, W, W0);

    // Phase 1: scatter pre-scaled X rows into agg
    int edges_per_block = (256 / 32) * 2 * EPH;   // 8 warps x 8 edges
    scatter_kernel<<<(E + edges_per_block - 1) / edges_per_block, 256>>>(esrc, edst, erel, inv_norm, E, N);

    // Phase 2: pipelined GEMM — out = X@W0 + sum_r agg_r @ W_r
    cudaFuncSetAttribute(gemm_fused_kernel, cudaFuncAttributeMaxDynamicSharedMemorySize, SMEM_TOTAL);
    gemm_fused_kernel<<<(N + 127) / 128, 256, SMEM_TOTAL>>>(out, N);
}